// round 1
// baseline (speedup 1.0000x reference)
#include <cuda_runtime.h>
#include <cuda_bf16.h>
#include <math.h>

// ---------------------------------------------------------------------------
// GriffinBlock baseline: fp32 everywhere.
// Shapes: B=4, T=2048, DIM=1024, HID=1536, GH=2048, K=4, HD=128, QH=8, W=1024
// M = B*T = 8192 rows for every GEMM.
// ---------------------------------------------------------------------------

#define Bdim 4
#define Tdim 2048
#define DIM 1024
#define HID 1536
#define GH  2048
#define KCONV 4
#define HD  128
#define QH  8
#define WIN 1024
#define MROWS (Bdim*Tdim)   // 8192

// ---------------- scratch pool (static device memory, no allocs) -----------
// xn:    8192*1024  =  8388608
// big:   8192*4096  = 33554432  (Win-out / grow-out / q+kv+attn_out)
// mid:   8192*3072  = 25165824  (Wg-out -> alpha/xs in place)
// small: 8192*2048  = 16777216  (hconv / hy / gated-mlp act)
#define OFF_XN    0u
#define OFF_BIG   8388608u
#define OFF_MID   41943040u   // 8388608+33554432
#define OFF_SMALL 67108864u   // +25165824
#define POOL_FLOATS 83886080u // +16777216

__device__ float g_pool[POOL_FLOATS];

__device__ __forceinline__ float gelu_exact(float x) {
    return 0.5f * x * (1.0f + erff(x * 0.70710678118654752f));
}
__device__ __forceinline__ float sigmoidf(float x) {
    return 1.0f / (1.0f + expf(-x));
}

// ---------------------------------------------------------------------------
// RMSNorm: y = gamma * sqrt(DIM) * x / ||x||   (one block per row, 256 thr)
// ---------------------------------------------------------------------------
__global__ void rmsnorm_kernel(const float* __restrict__ x,
                               const float* __restrict__ gamma,
                               float* __restrict__ y) {
    int row = blockIdx.x;
    int tid = threadIdx.x;
    const float4* xr = (const float4*)(x + (size_t)row * DIM);
    float4 v = xr[tid];
    float ss = v.x*v.x + v.y*v.y + v.z*v.z + v.w*v.w;
    #pragma unroll
    for (int o = 16; o; o >>= 1) ss += __shfl_xor_sync(0xffffffffu, ss, o);
    __shared__ float red[8];
    __shared__ float stot;
    if ((tid & 31) == 0) red[tid >> 5] = ss;
    __syncthreads();
    if (tid == 0) {
        float s = 0.f;
        #pragma unroll
        for (int i = 0; i < 8; i++) s += red[i];
        stot = s;
    }
    __syncthreads();
    float scale = 32.0f * rsqrtf(stot);   // sqrt(1024)=32
    float4 g = ((const float4*)gamma)[tid];
    float4 o;
    o.x = v.x * scale * g.x;
    o.y = v.y * scale * g.y;
    o.z = v.z * scale * g.z;
    o.w = v.w * scale * g.w;
    ((float4*)(y + (size_t)row * DIM))[tid] = o;
}

// ---------------------------------------------------------------------------
// SGEMM: C[M,N] = A[M,Kd] @ W[N,Kd]^T (+bias[N]) (+res[M,N])
// 128x128 tile, Kt=8, 256 threads, 8x8 per thread.
// Requires M%128==0, N%128==0, Kd%8==0 (true for all shapes here).
// ---------------------------------------------------------------------------
template<bool HAS_BIAS, bool HAS_RES>
__global__ void __launch_bounds__(256, 2)
sgemm_kernel(const float* __restrict__ A, const float* __restrict__ Wt,
             const float* __restrict__ bias, const float* __restrict__ res,
             float* __restrict__ C, int N, int Kd) {
    __shared__ float As[8 * 132];
    __shared__ float Bs[8 * 132];
    const int tid = threadIdx.x;
    const int m0 = blockIdx.y * 128;
    const int n0 = blockIdx.x * 128;
    const int lr = tid >> 1;
    const int lc = (tid & 1) * 4;
    const int ty = tid >> 4;
    const int tx = tid & 15;

    const float* Ap = A  + (size_t)(m0 + lr) * Kd + lc;
    const float* Bp = Wt + (size_t)(n0 + lr) * Kd + lc;

    float4 av = *(const float4*)Ap;
    float4 bv = *(const float4*)Bp;

    float acc[8][8];
    #pragma unroll
    for (int i = 0; i < 8; i++)
        #pragma unroll
        for (int j = 0; j < 8; j++) acc[i][j] = 0.f;

    for (int k0 = 0;;) {
        __syncthreads();
        As[(lc+0)*132 + lr] = av.x;
        As[(lc+1)*132 + lr] = av.y;
        As[(lc+2)*132 + lr] = av.z;
        As[(lc+3)*132 + lr] = av.w;
        Bs[(lc+0)*132 + lr] = bv.x;
        Bs[(lc+1)*132 + lr] = bv.y;
        Bs[(lc+2)*132 + lr] = bv.z;
        Bs[(lc+3)*132 + lr] = bv.w;
        __syncthreads();
        k0 += 8;
        if (k0 < Kd) {
            av = *(const float4*)(Ap + k0);
            bv = *(const float4*)(Bp + k0);
        }
        #pragma unroll
        for (int kk = 0; kk < 8; kk++) {
            float a[8], b[8];
            *(float4*)&a[0] = *(const float4*)&As[kk*132 + ty*8];
            *(float4*)&a[4] = *(const float4*)&As[kk*132 + ty*8 + 4];
            *(float4*)&b[0] = *(const float4*)&Bs[kk*132 + tx*8];
            *(float4*)&b[4] = *(const float4*)&Bs[kk*132 + tx*8 + 4];
            #pragma unroll
            for (int i = 0; i < 8; i++)
                #pragma unroll
                for (int j = 0; j < 8; j++)
                    acc[i][j] = fmaf(a[i], b[j], acc[i][j]);
        }
        if (k0 >= Kd) break;
    }

    #pragma unroll
    for (int i = 0; i < 8; i++) {
        int m = m0 + ty*8 + i;
        float* Cp = C + (size_t)m * N + n0 + tx*8;
        #pragma unroll
        for (int jj = 0; jj < 2; jj++) {
            float4 v;
            v.x = acc[i][jj*4+0]; v.y = acc[i][jj*4+1];
            v.z = acc[i][jj*4+2]; v.w = acc[i][jj*4+3];
            if (HAS_BIAS) {
                const float* bp = bias + n0 + tx*8 + jj*4;
                v.x += bp[0]; v.y += bp[1]; v.z += bp[2]; v.w += bp[3];
            }
            if (HAS_RES) {
                float4 rv = *(const float4*)(res + (size_t)m * N + n0 + tx*8 + jj*4);
                v.x += rv.x; v.y += rv.y; v.z += rv.z; v.w += rv.w;
            }
            *(float4*)(Cp + jj*4) = v;
        }
    }
}

static void launch_gemm(const float* A, const float* Wt, const float* bias,
                        const float* res, float* C, int N, int Kd) {
    dim3 grid(N / 128, MROWS / 128);
    if (bias && res)      sgemm_kernel<true , true ><<<grid, 256>>>(A, Wt, bias, res, C, N, Kd);
    else if (bias)        sgemm_kernel<true , false><<<grid, 256>>>(A, Wt, bias, res, C, N, Kd);
    else if (res)         sgemm_kernel<false, true ><<<grid, 256>>>(A, Wt, bias, res, C, N, Kd);
    else                  sgemm_kernel<false, false><<<grid, 256>>>(A, Wt, bias, res, C, N, Kd);
}

// ---------------------------------------------------------------------------
// hawk depthwise causal conv (K=4) over time + bias.
// gh layout: [bt][3072], h part at cols [1536..3072). Out: hconv[bt][1536].
// ---------------------------------------------------------------------------
__global__ void conv_kernel(const float* __restrict__ gh,
                            const float* __restrict__ cw,
                            const float* __restrict__ cb,
                            float* __restrict__ hconv) {
    int idx = blockIdx.x * blockDim.x + threadIdx.x;
    if (idx >= MROWS * HID) return;
    int c = idx % HID;
    int bt = idx / HID;
    int t = bt & (Tdim - 1);
    int b = bt >> 11;
    float acc = cb[c];
    #pragma unroll
    for (int k = 0; k < KCONV; k++) {
        int tt = t - (KCONV - 1) + k;
        if (tt >= 0)
            acc += cw[c*KCONV + k] * gh[(size_t)(b*Tdim + tt) * (2*HID) + HID + c];
    }
    hconv[(size_t)bt * HID + c] = acc;
}

// ---------------------------------------------------------------------------
// gates: gi[bt][3072] = [forget | inp] -> overwritten with [alpha | xs]
// ---------------------------------------------------------------------------
__global__ void gates_kernel(float* __restrict__ gi,
                             const float* __restrict__ hconv,
                             const float* __restrict__ fb) {
    int idx = blockIdx.x * blockDim.x + threadIdx.x;
    if (idx >= MROWS * HID) return;
    int c = idx % HID;
    size_t bt = idx / HID;
    float f  = gi[bt * (2*HID) + c];
    float ip = gi[bt * (2*HID) + HID + c];
    float h  = hconv[bt * HID + c];
    float sp = log1pf(expf(fb[c]));          // softplus(fb)
    float alpha = expf(-8.0f * sp * sigmoidf(f));
    float beta  = sqrtf(1.0f - alpha*alpha + 1e-6f);
    gi[bt * (2*HID) + c]        = alpha;
    gi[bt * (2*HID) + HID + c]  = beta * sigmoidf(ip) * h;
}

// ---------------------------------------------------------------------------
// scan: hstate_t = alpha_t * hstate_{t-1} + xs_t ; hy = gelu(gate)*hstate
// one thread per (b, channel) -> 6144 threads, sequential over T.
// ---------------------------------------------------------------------------
__global__ void scan_kernel(const float* __restrict__ gi,
                            const float* __restrict__ gh,
                            float* __restrict__ hy) {
    int idx = blockIdx.x * blockDim.x + threadIdx.x;
    if (idx >= Bdim * HID) return;
    int c = idx % HID;
    int b = idx / HID;
    size_t base  = (size_t)b * Tdim * (2*HID) + c;
    size_t obase = (size_t)b * Tdim * HID + c;
    float st = 0.f;
    for (int t = 0; t < Tdim; t++) {
        size_t o = base + (size_t)t * (2*HID);
        float a  = gi[o];
        float xv = gi[o + HID];
        float g  = gh[o];
        st = fmaf(a, st, xv);
        hy[obase + (size_t)t * HID] = gelu_exact(g) * st;
    }
}

// ---------------------------------------------------------------------------
// gated-MLP activation: out[bt][2048] = gelu(grow[:, :2048]) * grow[:, 2048:]
// ---------------------------------------------------------------------------
__global__ void gelugate_kernel(const float* __restrict__ grow,
                                float* __restrict__ out) {
    int idx = blockIdx.x * blockDim.x + threadIdx.x;
    if (idx >= MROWS * GH) return;
    int c  = idx & (GH - 1);
    size_t bt = idx >> 11;
    float g = grow[bt * (2*GH) + c];
    float h = grow[bt * (2*GH) + GH + c];
    out[idx] = gelu_exact(g) * h;
}

// ---------------------------------------------------------------------------
// rotary: in-place on q [bt][QH*HD] and k (cols 0..127 of kv [bt][256])
// ---------------------------------------------------------------------------
__global__ void rotary_kernel(float* __restrict__ q, float* __restrict__ kv) {
    const int NQ = MROWS * QH * (HD/2);       // 4,194,304
    const int NK = MROWS * (HD/2);            //   524,288
    int idx = blockIdx.x * blockDim.x + threadIdx.x;
    if (idx >= NQ + NK) return;
    float* p;
    int t, i;
    if (idx < NQ) {
        i = idx & 63;
        int r = idx >> 6;
        int h = r & 7;
        int bt = r >> 3;
        t = bt & (Tdim - 1);
        p = q + (size_t)bt * (QH*HD) + h*HD + 2*i;
    } else {
        int j = idx - NQ;
        i = j & 63;
        int bt = j >> 6;
        t = bt & (Tdim - 1);
        p = kv + (size_t)bt * (2*HD) + 2*i;
    }
    // inv_freq = 10000^(-2i/128)
    float inv = expf(-(float)(2*i) * (9.210340371976184f / 128.0f));
    float ang = (float)t * inv;
    float sn, cs;
    sincosf(ang, &sn, &cs);
    float x0 = p[0], x1 = p[1];
    p[0] = x0*cs - x1*sn;
    p[1] = x1*cs + x0*sn;
}

// ---------------------------------------------------------------------------
// sliding-window attention (flash-style, fp32).
// Query attends keys g in [t-WIN, t], g>=0.  64 q-rows/block, 64-key tiles.
// grid: (T/64, QH, B), 256 threads, dynamic smem ~121.6KB.
// ---------------------------------------------------------------------------
#define ATT_MQ 64
#define ATT_NK 64
#define SM_Q  (128*68)
#define SM_K  (128*68)
#define SM_V  (64*132)
#define SM_P  (64*68)
#define ATT_SMEM_FLOATS (SM_Q + SM_K + SM_V + SM_P + 3*64)

__global__ void attn_kernel(const float* __restrict__ q,
                            const float* __restrict__ kv,
                            float* __restrict__ out) {
    extern __shared__ float sm[];
    float* sQ   = sm;
    float* sK   = sQ + SM_Q;
    float* sV   = sK + SM_K;
    float* sP   = sV + SM_V;
    float* rowm = sP + SM_P;
    float* rowl = rowm + 64;
    float* rowsc = rowl + 64;

    const int tid = threadIdx.x;
    const int b  = blockIdx.z;
    const int h  = blockIdx.y;
    const int q0 = blockIdx.x * ATT_MQ;

    // load Q tile transposed: sQ[d][r]
    for (int u = tid; u < 64*32; u += 256) {
        int r  = u >> 5;
        int cs = (u & 31) * 4;
        float4 v = *(const float4*)(q + (size_t)(b*Tdim + q0 + r)*(QH*HD) + h*HD + cs);
        sQ[(cs+0)*68 + r] = v.x;
        sQ[(cs+1)*68 + r] = v.y;
        sQ[(cs+2)*68 + r] = v.z;
        sQ[(cs+3)*68 + r] = v.w;
    }
    if (tid < 64) { rowm[tid] = -1e30f; rowl[tid] = 0.f; }

    const int tys = tid >> 4;      // query row group (also PV row group)
    const int txs = tid & 15;      // key group / dim group
    float oacc[4][8];
    #pragma unroll
    for (int i = 0; i < 4; i++)
        #pragma unroll
        for (int j = 0; j < 8; j++) oacc[i][j] = 0.f;

    for (int tile = 0; tile < 17; tile++) {
        int kstart = q0 - WIN + tile * ATT_NK;
        if (kstart + ATT_NK - 1 < 0) continue;   // uniform across block

        __syncthreads();  // previous tile fully consumed (also covers Q load)

        // load K (transposed) and V tiles, zero-fill g<0
        for (int u = tid; u < 64*32; u += 256) {
            int r  = u >> 5;
            int cs = (u & 31) * 4;
            int g = kstart + r;
            float4 kk = make_float4(0.f,0.f,0.f,0.f);
            float4 vv = make_float4(0.f,0.f,0.f,0.f);
            if (g >= 0) {
                const float* base = kv + (size_t)(b*Tdim + g) * (2*HD);
                kk = *(const float4*)(base + cs);
                vv = *(const float4*)(base + HD + cs);
            }
            sK[(cs+0)*68 + r] = kk.x;
            sK[(cs+1)*68 + r] = kk.y;
            sK[(cs+2)*68 + r] = kk.z;
            sK[(cs+3)*68 + r] = kk.w;
            *(float4*)&sV[r*132 + cs] = vv;
        }
        __syncthreads();

        // scores S = Q K^T / sqrt(HD), masked -> sP[j][r]
        {
            float sacc[4][4];
            #pragma unroll
            for (int i = 0; i < 4; i++)
                #pragma unroll
                for (int j = 0; j < 4; j++) sacc[i][j] = 0.f;
            #pragma unroll 8
            for (int kk = 0; kk < HD; kk++) {
                float4 aq = *(const float4*)&sQ[kk*68 + tys*4];
                float4 bk = *(const float4*)&sK[kk*68 + txs*4];
                float a[4] = {aq.x, aq.y, aq.z, aq.w};
                float bb[4] = {bk.x, bk.y, bk.z, bk.w};
                #pragma unroll
                for (int i = 0; i < 4; i++)
                    #pragma unroll
                    for (int j = 0; j < 4; j++)
                        sacc[i][j] = fmaf(a[i], bb[j], sacc[i][j]);
            }
            #pragma unroll
            for (int i = 0; i < 4; i++) {
                int r = tys*4 + i;
                int t = q0 + r;
                #pragma unroll
                for (int j = 0; j < 4; j++) {
                    int g = kstart + txs*4 + j;
                    float s = sacc[i][j] * 0.088388347648318447f;
                    bool valid = (g >= 0) && (g <= t) && (g >= t - WIN);
                    sP[(txs*4 + j)*68 + r] = valid ? s : -1e30f;
                }
            }
        }
        __syncthreads();

        // online softmax per row (threads 0..63)
        if (tid < 64) {
            int r = tid;
            float m_old = rowm[r];
            float mx = m_old;
            #pragma unroll 8
            for (int j = 0; j < 64; j++) mx = fmaxf(mx, sP[j*68 + r]);
            float sum = 0.f;
            #pragma unroll 8
            for (int j = 0; j < 64; j++) {
                float p = expf(sP[j*68 + r] - mx);
                sP[j*68 + r] = p;
                sum += p;
            }
            float sc = expf(m_old - mx);
            rowl[r] = rowl[r] * sc + sum;
            rowm[r] = mx;
            rowsc[r] = sc;
        }
        __syncthreads();

        // rescale accumulators, then O += P V
        #pragma unroll
        for (int i = 0; i < 4; i++) {
            float sc = rowsc[tys*4 + i];
            #pragma unroll
            for (int j = 0; j < 8; j++) oacc[i][j] *= sc;
        }
        #pragma unroll 4
        for (int j = 0; j < ATT_NK; j++) {
            float4 pa = *(const float4*)&sP[j*68 + tys*4];
            float4 v0 = *(const float4*)&sV[j*132 + txs*8];
            float4 v1 = *(const float4*)&sV[j*132 + txs*8 + 4];
            float pr[4] = {pa.x, pa.y, pa.z, pa.w};
            float vb[8] = {v0.x, v0.y, v0.z, v0.w, v1.x, v1.y, v1.z, v1.w};
            #pragma unroll
            for (int i = 0; i < 4; i++)
                #pragma unroll
                for (int d = 0; d < 8; d++)
                    oacc[i][d] = fmaf(pr[i], vb[d], oacc[i][d]);
        }
    }

    // normalize and store: out[bt][h*HD + d]
    #pragma unroll
    for (int i = 0; i < 4; i++) {
        int r = tys*4 + i;
        float invl = 1.0f / rowl[r];
        float* op = out + (size_t)(b*Tdim + q0 + r)*(QH*HD) + h*HD + txs*8;
        float4 w0, w1;
        w0.x = oacc[i][0]*invl; w0.y = oacc[i][1]*invl;
        w0.z = oacc[i][2]*invl; w0.w = oacc[i][3]*invl;
        w1.x = oacc[i][4]*invl; w1.y = oacc[i][5]*invl;
        w1.z = oacc[i][6]*invl; w1.w = oacc[i][7]*invl;
        *(float4*)op = w0;
        *(float4*)(op + 4) = w1;
    }
}

// ---------------------------------------------------------------------------
// launch
// ---------------------------------------------------------------------------
extern "C" void kernel_launch(void* const* d_in, const int* in_sizes, int n_in,
                              void* d_out, int out_size) {
    const float* x         = (const float*)d_in[0];
    const float* gn_hawk   = (const float*)d_in[1];
    const float* gn_hgmlp  = (const float*)d_in[2];
    const float* gn_smqa   = (const float*)d_in[3];
    const float* gn_sgmlp  = (const float*)d_in[4];
    const float* hawk_Win  = (const float*)d_in[5];
    const float* hawk_cw   = (const float*)d_in[6];
    const float* hawk_cb   = (const float*)d_in[7];
    const float* hawk_Wg   = (const float*)d_in[8];
    const float* hawk_bg   = (const float*)d_in[9];
    const float* hawk_fb   = (const float*)d_in[10];
    const float* hawk_Wout = (const float*)d_in[11];
    const float* g1_Wgrow  = (const float*)d_in[12];
    const float* g1_Wshr   = (const float*)d_in[13];
    const float* g2_Wgrow  = (const float*)d_in[14];
    const float* g2_Wshr   = (const float*)d_in[15];
    const float* smqa_Wq   = (const float*)d_in[16];
    const float* smqa_Wkv  = (const float*)d_in[17];
    const float* smqa_Wout = (const float*)d_in[18];
    float* out = (float*)d_out;

    float* pool = nullptr;
    cudaGetSymbolAddress((void**)&pool, g_pool);
    float* xn    = pool + OFF_XN;
    float* big   = pool + OFF_BIG;
    float* mid   = pool + OFF_MID;
    float* small = pool + OFF_SMALL;

    static const size_t ATT_SMEM_BYTES = ATT_SMEM_FLOATS * sizeof(float);
    cudaFuncSetAttribute((const void*)attn_kernel,
                         cudaFuncAttributeMaxDynamicSharedMemorySize,
                         (int)ATT_SMEM_BYTES);

    const int EW = 256;

    // ---------------- stage 1: hawk ----------------
    rmsnorm_kernel<<<MROWS, 256>>>(x, gn_hawk, xn);
    launch_gemm(xn, hawk_Win, nullptr, nullptr, big, 2*HID, DIM);            // gh
    conv_kernel<<<(MROWS*HID)/EW, EW>>>(big, hawk_cw, hawk_cb, small);       // hconv
    launch_gemm(small, hawk_Wg, hawk_bg, nullptr, mid, 2*HID, HID);          // gi
    gates_kernel<<<(MROWS*HID)/EW, EW>>>(mid, small, hawk_fb);               // alpha/xs in place
    scan_kernel<<<(Bdim*HID + EW - 1)/EW, EW>>>(mid, big, small);            // hy
    launch_gemm(small, hawk_Wout, nullptr, x, out, DIM, HID);                // out = x + hy@Wout^T

    // ---------------- stage 2: gated MLP 1 ----------------
    rmsnorm_kernel<<<MROWS, 256>>>(out, gn_hgmlp, xn);
    launch_gemm(xn, g1_Wgrow, nullptr, nullptr, big, 2*GH, DIM);
    gelugate_kernel<<<(MROWS*GH)/EW, EW>>>(big, small);
    launch_gemm(small, g1_Wshr, nullptr, out, out, DIM, GH);

    // ---------------- stage 3: sliding-window MQA ----------------
    rmsnorm_kernel<<<MROWS, 256>>>(out, gn_smqa, xn);
    float* qb  = big;
    float* kvb = big + (size_t)MROWS * (QH*HD);        // +8M floats
    float* ao  = big + 2u * (size_t)MROWS * (QH*HD);   // +16M floats
    launch_gemm(xn, smqa_Wq, nullptr, nullptr, qb, QH*HD, DIM);
    launch_gemm(xn, smqa_Wkv, nullptr, nullptr, kvb, 2*HD, DIM);
    {
        int total = MROWS*QH*(HD/2) + MROWS*(HD/2);
        rotary_kernel<<<(total + EW - 1)/EW, EW>>>(qb, kvb);
    }
    attn_kernel<<<dim3(Tdim/ATT_MQ, QH, Bdim), 256, ATT_SMEM_BYTES>>>(qb, kvb, ao);
    launch_gemm(ao, smqa_Wout, nullptr, out, out, DIM, DIM);

    // ---------------- stage 4: gated MLP 2 ----------------
    rmsnorm_kernel<<<MROWS, 256>>>(out, gn_sgmlp, xn);
    launch_gemm(xn, g2_Wgrow, nullptr, nullptr, big, 2*GH, DIM);
    gelugate_kernel<<<(MROWS*GH)/EW, EW>>>(big, small);
    launch_gemm(small, g2_Wshr, nullptr, out, out, DIM, GH);
}

// round 4
// speedup vs baseline: 2.0923x; 2.0923x over previous
#include <cuda_runtime.h>
#include <cuda_bf16.h>
#include <math.h>
#include <stdint.h>

// ---------------------------------------------------------------------------
// GriffinBlock: HMMA (mma.sync bf16x3) GEMMs + fp32 flash attention
// B=4, T=2048, DIM=1024, HID=1536, GH=2048, K=4, HD=128, QH=8, W=1024
// ---------------------------------------------------------------------------

#define Bdim 4
#define Tdim 2048
#define DIM 1024
#define HID 1536
#define GH  2048
#define KCONV 4
#define HD  128
#define QH  8
#define WINSZ 1024
#define MROWS (Bdim*Tdim)   // 8192

// ---------------- static scratch ----------------
__device__ float g_big[33554432];      // 8192*4096
__device__ float g_mid[25165824];      // 8192*3072
__device__ float g_small[12582912];    // 8192*1536
__device__ __nv_bfloat16 g_Ahi[16777216];  // 8192*2048 max
__device__ __nv_bfloat16 g_Alo[16777216];
__device__ __nv_bfloat16 g_Whi[4718592];   // 3072*1536 max
__device__ __nv_bfloat16 g_Wlo[4718592];

__device__ __forceinline__ float gelu_exact(float x) {
    return 0.5f * x * (1.0f + erff(x * 0.70710678118654752f));
}
__device__ __forceinline__ float sigmoidf_(float x) {
    return 1.0f / (1.0f + expf(-x));
}
__device__ __forceinline__ void split_bf16(float v, __nv_bfloat16& h, __nv_bfloat16& l) {
    h = __float2bfloat16(v);
    l = __float2bfloat16(v - __bfloat162float(h));
}

__device__ __forceinline__ uint32_t smem_u32(const void* p) {
    uint32_t a;
    asm("{ .reg .u64 t; cvta.to.shared.u64 t, %1; cvt.u32.u64 %0, t; }" : "=r"(a) : "l"(p));
    return a;
}
__device__ __forceinline__ void cp16(uint32_t dst, const void* src) {
    asm volatile("cp.async.ca.shared.global [%0], [%1], 16;" :: "r"(dst), "l"(src));
}

#define LDSM4(r0, r1, r2, r3, addr) \
    asm volatile("ldmatrix.sync.aligned.m8n8.x4.shared.b16 {%0,%1,%2,%3}, [%4];" \
        : "=r"(r0), "=r"(r1), "=r"(r2), "=r"(r3) : "r"(addr))

#define MMA_BF16(d, a, b) \
    asm volatile("mma.sync.aligned.m16n8k16.row.col.f32.bf16.bf16.f32 " \
        "{%0,%1,%2,%3}, {%4,%5,%6,%7}, {%8,%9}, {%0,%1,%2,%3};" \
        : "+f"((d)[0]), "+f"((d)[1]), "+f"((d)[2]), "+f"((d)[3]) \
        : "r"((a)[0]), "r"((a)[1]), "r"((a)[2]), "r"((a)[3]), \
          "r"((b)[0]), "r"((b)[1]))

// ---------------------------------------------------------------------------
// bf16x3 HMMA GEMM: C[M,N] = (Ahi+Alo)[M,K] @ (Whi+Wlo)[N,K]^T (+bias)(+res)
// CTA tile 128x128, K-chunk 64, 256 threads (8 warps, 4x2), warp tile 32x64.
// 2-stage cp.async pipeline. fp32 accumulate in registers.
// ---------------------------------------------------------------------------
#define CTM 128
#define CTN 128
#define CTK 64
#define APITCH 72                       // bf16 elems per smem row (pad 64->72)
#define OFF_SALO_B 18432u               // byte offsets within a stage
#define OFF_SBHI_B 36864u
#define OFF_SBLO_B 55296u
#define STAGE_BYTES 73728u
#define GEMM_SMEM_BYTES (2u*STAGE_BYTES)  // 147456

template<bool HAS_BIAS, bool HAS_RES>
__global__ void __launch_bounds__(256, 1)
bgemm_kernel(const __nv_bfloat16* __restrict__ Ahi, const __nv_bfloat16* __restrict__ Alo,
             const __nv_bfloat16* __restrict__ Whi, const __nv_bfloat16* __restrict__ Wlo,
             const float* __restrict__ bias, const float* __restrict__ res,
             float* __restrict__ C, int N, int K) {
    extern __shared__ char smc[];
    const uint32_t sb = smem_u32(smc);
    const int tid = threadIdx.x;
    const int lane = tid & 31;
    const int wid = tid >> 5;
    const int wy = wid & 3;            // 4 warp-rows of 32
    const int wx = wid >> 2;           // 2 warp-cols of 64
    const int m0 = blockIdx.y * CTM;
    const int n0 = blockIdx.x * CTN;

    // ldmatrix per-lane base offsets (bytes, within a stage)
    const int arow = wy*32 + (lane & 15);
    const int acol = (lane >> 4) * 8;
    const uint32_t aoff = (uint32_t)(arow*APITCH + acol) * 2u;
    const int g  = lane >> 3;
    const int rr = lane & 7;
    const int brow = wx*64 + rr + ((g >> 1) << 3);
    const int bcol = (g & 1) * 8;
    const uint32_t boff = (uint32_t)(brow*APITCH + bcol) * 2u;

    float acc[2][8][4];
    #pragma unroll
    for (int i = 0; i < 2; i++)
        #pragma unroll
        for (int j = 0; j < 8; j++)
            #pragma unroll
            for (int v = 0; v < 4; v++) acc[i][j][v] = 0.f;

    const int NC = K / CTK;

    // stage loader: 128 rows x 8 chunks of 16B per matrix (full 64 k-columns)
    #define LOAD_STAGE(stg, kb) do { \
        uint32_t sbase_ = sb + (stg)*STAGE_BYTES; \
        _Pragma("unroll") \
        for (int it_ = 0; it_ < 4; it_++) { \
            int u_ = tid + it_*256; \
            int r_ = u_ >> 3; \
            int c_ = u_ & 7; \
            uint32_t d_ = sbase_ + (uint32_t)r_*144u + (uint32_t)c_*16u; \
            size_t ga_ = (size_t)(m0 + r_) * K + (kb) + c_*8; \
            size_t gb_ = (size_t)(n0 + r_) * K + (kb) + c_*8; \
            cp16(d_,              Ahi + ga_); \
            cp16(d_ + OFF_SALO_B, Alo + ga_); \
            cp16(d_ + OFF_SBHI_B, Whi + gb_); \
            cp16(d_ + OFF_SBLO_B, Wlo + gb_); \
        } \
        asm volatile("cp.async.commit_group;"); \
    } while (0)

    LOAD_STAGE(0, 0);

    for (int ch = 0; ch < NC; ch++) {
        const int stg = ch & 1;
        if (ch + 1 < NC) {
            LOAD_STAGE(stg ^ 1, (ch + 1) * CTK);
            asm volatile("cp.async.wait_group 1;");
        } else {
            asm volatile("cp.async.wait_group 0;");
        }
        __syncthreads();

        const uint32_t sbase = sb + stg * STAGE_BYTES;
        #pragma unroll
        for (int k16 = 0; k16 < 4; k16++) {
            uint32_t ah[2][4], al[2][4], bh[8][2], bl[8][2];
            #pragma unroll
            for (int mt = 0; mt < 2; mt++) {
                uint32_t ad = sbase + aoff + (uint32_t)mt*(16*APITCH*2) + (uint32_t)k16*32u;
                LDSM4(ah[mt][0], ah[mt][1], ah[mt][2], ah[mt][3], ad);
                LDSM4(al[mt][0], al[mt][1], al[mt][2], al[mt][3], ad + OFF_SALO_B);
            }
            #pragma unroll
            for (int jp = 0; jp < 4; jp++) {
                uint32_t bd = sbase + boff + (uint32_t)jp*(16*APITCH*2) + (uint32_t)k16*32u;
                LDSM4(bh[2*jp][0], bh[2*jp][1], bh[2*jp+1][0], bh[2*jp+1][1], bd + OFF_SBHI_B);
                LDSM4(bl[2*jp][0], bl[2*jp][1], bl[2*jp+1][0], bl[2*jp+1][1], bd + OFF_SBLO_B);
            }
            #pragma unroll
            for (int mt = 0; mt < 2; mt++)
                #pragma unroll
                for (int j = 0; j < 8; j++) {
                    MMA_BF16(acc[mt][j], ah[mt], bh[j]);
                    MMA_BF16(acc[mt][j], ah[mt], bl[j]);
                    MMA_BF16(acc[mt][j], al[mt], bh[j]);
                }
        }
        __syncthreads();
    }
    #undef LOAD_STAGE

    // epilogue
    const int rbase = m0 + wy*32 + (lane >> 2);
    const int cbase = n0 + wx*64 + (lane & 3)*2;
    #pragma unroll
    for (int mt = 0; mt < 2; mt++) {
        #pragma unroll
        for (int half = 0; half < 2; half++) {
            const int row = rbase + mt*16 + half*8;
            #pragma unroll
            for (int j = 0; j < 8; j++) {
                const int col = cbase + j*8;
                float v0 = acc[mt][j][half*2 + 0];
                float v1 = acc[mt][j][half*2 + 1];
                if (HAS_BIAS) { v0 += bias[col]; v1 += bias[col + 1]; }
                if (HAS_RES) {
                    const float2 rv = *(const float2*)(res + (size_t)row * N + col);
                    v0 += rv.x; v1 += rv.y;
                }
                float2 o; o.x = v0; o.y = v1;
                *(float2*)(C + (size_t)row * N + col) = o;
            }
        }
    }
}

// ---------------------------------------------------------------------------
// weight fp32 -> bf16 hi/lo
// ---------------------------------------------------------------------------
__global__ void convw_kernel(const float* __restrict__ s,
                             __nv_bfloat16* __restrict__ hi,
                             __nv_bfloat16* __restrict__ lo, int n4) {
    int i = blockIdx.x * blockDim.x + threadIdx.x;
    if (i >= n4) return;
    float4 v = ((const float4*)s)[i];
    __nv_bfloat16 h0, h1, h2, h3, l0, l1, l2, l3;
    split_bf16(v.x, h0, l0); split_bf16(v.y, h1, l1);
    split_bf16(v.z, h2, l2); split_bf16(v.w, h3, l3);
    __nv_bfloat162* hp = (__nv_bfloat162*)hi;
    __nv_bfloat162* lp = (__nv_bfloat162*)lo;
    hp[2*i]   = __nv_bfloat162(h0, h1);
    hp[2*i+1] = __nv_bfloat162(h2, h3);
    lp[2*i]   = __nv_bfloat162(l0, l1);
    lp[2*i+1] = __nv_bfloat162(l2, l3);
}

// ---------------------------------------------------------------------------
// RMSNorm -> bf16 hi/lo
// ---------------------------------------------------------------------------
__global__ void rmsnorm_bf16_kernel(const float* __restrict__ x,
                                    const float* __restrict__ gamma,
                                    __nv_bfloat16* __restrict__ hi,
                                    __nv_bfloat16* __restrict__ lo) {
    int row = blockIdx.x;
    int tid = threadIdx.x;
    float4 v = ((const float4*)(x + (size_t)row * DIM))[tid];
    float ss = v.x*v.x + v.y*v.y + v.z*v.z + v.w*v.w;
    #pragma unroll
    for (int o = 16; o; o >>= 1) ss += __shfl_xor_sync(0xffffffffu, ss, o);
    __shared__ float red[8];
    __shared__ float stot;
    if ((tid & 31) == 0) red[tid >> 5] = ss;
    __syncthreads();
    if (tid == 0) {
        float s = 0.f;
        #pragma unroll
        for (int i = 0; i < 8; i++) s += red[i];
        stot = s;
    }
    __syncthreads();
    float scale = 32.0f * rsqrtf(stot);
    float4 g = ((const float4*)gamma)[tid];
    float o0 = v.x*scale*g.x, o1 = v.y*scale*g.y, o2 = v.z*scale*g.z, o3 = v.w*scale*g.w;
    __nv_bfloat16 h0,h1,h2,h3,l0,l1,l2,l3;
    split_bf16(o0,h0,l0); split_bf16(o1,h1,l1); split_bf16(o2,h2,l2); split_bf16(o3,h3,l3);
    __nv_bfloat162* hp = (__nv_bfloat162*)(hi + (size_t)row * DIM);
    __nv_bfloat162* lp = (__nv_bfloat162*)(lo + (size_t)row * DIM);
    hp[2*tid]   = __nv_bfloat162(h0,h1);
    hp[2*tid+1] = __nv_bfloat162(h2,h3);
    lp[2*tid]   = __nv_bfloat162(l0,l1);
    lp[2*tid+1] = __nv_bfloat162(l2,l3);
}

// ---------------------------------------------------------------------------
// hawk depthwise causal conv (K=4): fp32 out + bf16 hi/lo out
// ---------------------------------------------------------------------------
__global__ void conv_kernel(const float* __restrict__ gh,
                            const float* __restrict__ cw,
                            const float* __restrict__ cb,
                            float* __restrict__ hconv,
                            __nv_bfloat16* __restrict__ hi,
                            __nv_bfloat16* __restrict__ lo) {
    int idx = blockIdx.x * blockDim.x + threadIdx.x;
    if (idx >= MROWS * HID) return;
    int c = idx % HID;
    int bt = idx / HID;
    int t = bt & (Tdim - 1);
    int b = bt >> 11;
    float acc = cb[c];
    #pragma unroll
    for (int k = 0; k < KCONV; k++) {
        int tt = t - (KCONV - 1) + k;
        if (tt >= 0)
            acc += cw[c*KCONV + k] * gh[(size_t)(b*Tdim + tt) * (2*HID) + HID + c];
    }
    hconv[(size_t)bt * HID + c] = acc;
    __nv_bfloat16 h, l; split_bf16(acc, h, l);
    hi[(size_t)bt * HID + c] = h;
    lo[(size_t)bt * HID + c] = l;
}

// ---------------------------------------------------------------------------
// gates: gi[bt][3072] = [forget|inp] -> [alpha|xs] in place
// ---------------------------------------------------------------------------
__global__ void gates_kernel(float* __restrict__ gi,
                             const float* __restrict__ hconv,
                             const float* __restrict__ fb) {
    int idx = blockIdx.x * blockDim.x + threadIdx.x;
    if (idx >= MROWS * HID) return;
    int c = idx % HID;
    size_t bt = idx / HID;
    float f  = gi[bt * (2*HID) + c];
    float ip = gi[bt * (2*HID) + HID + c];
    float h  = hconv[bt * HID + c];
    float sp = log1pf(expf(fb[c]));
    float alpha = expf(-8.0f * sp * sigmoidf_(f));
    float beta  = sqrtf(1.0f - alpha*alpha + 1e-6f);
    gi[bt * (2*HID) + c]       = alpha;
    gi[bt * (2*HID) + HID + c] = beta * sigmoidf_(ip) * h;
}

// ---------------------------------------------------------------------------
// scan over T, then gelu(gate)*state -> bf16 hi/lo
// ---------------------------------------------------------------------------
__global__ void scan_kernel(const float* __restrict__ gi,
                            const float* __restrict__ gh,
                            __nv_bfloat16* __restrict__ hi,
                            __nv_bfloat16* __restrict__ lo) {
    int idx = blockIdx.x * blockDim.x + threadIdx.x;
    if (idx >= Bdim * HID) return;
    int c = idx % HID;
    int b = idx / HID;
    size_t base  = (size_t)b * Tdim * (2*HID) + c;
    size_t obase = (size_t)b * Tdim * HID + c;
    float st = 0.f;
    for (int t = 0; t < Tdim; t++) {
        size_t o = base + (size_t)t * (2*HID);
        float a  = gi[o];
        float xv = gi[o + HID];
        float g  = gh[o];
        st = fmaf(a, st, xv);
        float y = gelu_exact(g) * st;
        __nv_bfloat16 h, l; split_bf16(y, h, l);
        hi[obase + (size_t)t * HID] = h;
        lo[obase + (size_t)t * HID] = l;
    }
}

// ---------------------------------------------------------------------------
// gated-MLP activation -> bf16 hi/lo
// ---------------------------------------------------------------------------
__global__ void gelugate_kernel(const float* __restrict__ grow,
                                __nv_bfloat16* __restrict__ hi,
                                __nv_bfloat16* __restrict__ lo) {
    int idx = blockIdx.x * blockDim.x + threadIdx.x;
    if (idx >= MROWS * GH) return;
    int c  = idx & (GH - 1);
    size_t bt = idx >> 11;
    float g = grow[bt * (2*GH) + c];
    float h = grow[bt * (2*GH) + GH + c];
    float y = gelu_exact(g) * h;
    __nv_bfloat16 hh, ll; split_bf16(y, hh, ll);
    hi[idx] = hh;
    lo[idx] = ll;
}

// ---------------------------------------------------------------------------
// rotary in-place on q and k
// ---------------------------------------------------------------------------
__global__ void rotary_kernel(float* __restrict__ q, float* __restrict__ kv) {
    const int NQ = MROWS * QH * (HD/2);
    const int NK = MROWS * (HD/2);
    int idx = blockIdx.x * blockDim.x + threadIdx.x;
    if (idx >= NQ + NK) return;
    float* p;
    int t, i;
    if (idx < NQ) {
        i = idx & 63;
        int r = idx >> 6;
        int h = r & 7;
        int bt = r >> 3;
        t = bt & (Tdim - 1);
        p = q + (size_t)bt * (QH*HD) + h*HD + 2*i;
    } else {
        int j = idx - NQ;
        i = j & 63;
        int bt = j >> 6;
        t = bt & (Tdim - 1);
        p = kv + (size_t)bt * (2*HD) + 2*i;
    }
    float inv = expf(-(float)(2*i) * (9.210340371976184f / 128.0f));
    float ang = (float)t * inv;
    float sn, cs;
    sincosf(ang, &sn, &cs);
    float x0 = p[0], x1 = p[1];
    p[0] = x0*cs - x1*sn;
    p[1] = x1*cs + x0*sn;
}

// ---------------------------------------------------------------------------
// flash attention fp32 -> bf16 hi/lo output (A operand of Wout GEMM)
// ---------------------------------------------------------------------------
#define ATT_MQ 64
#define ATT_NK 64
#define SM_Q  (128*68)
#define SM_K  (128*68)
#define SM_V  (64*132)
#define SM_P  (64*68)
#define ATT_SMEM_FLOATS (SM_Q + SM_K + SM_V + SM_P + 3*64)

__global__ void attn_kernel(const float* __restrict__ q,
                            const float* __restrict__ kv,
                            __nv_bfloat16* __restrict__ ohi,
                            __nv_bfloat16* __restrict__ olo) {
    extern __shared__ float sm[];
    float* sQ   = sm;
    float* sK   = sQ + SM_Q;
    float* sV   = sK + SM_K;
    float* sP   = sV + SM_V;
    float* rowm = sP + SM_P;
    float* rowl = rowm + 64;
    float* rowsc = rowl + 64;

    const int tid = threadIdx.x;
    const int b  = blockIdx.z;
    const int h  = blockIdx.y;
    const int q0 = blockIdx.x * ATT_MQ;

    for (int u = tid; u < 64*32; u += 256) {
        int r  = u >> 5;
        int cs = (u & 31) * 4;
        float4 v = *(const float4*)(q + (size_t)(b*Tdim + q0 + r)*(QH*HD) + h*HD + cs);
        sQ[(cs+0)*68 + r] = v.x;
        sQ[(cs+1)*68 + r] = v.y;
        sQ[(cs+2)*68 + r] = v.z;
        sQ[(cs+3)*68 + r] = v.w;
    }
    if (tid < 64) { rowm[tid] = -1e30f; rowl[tid] = 0.f; }

    const int tys = tid >> 4;
    const int txs = tid & 15;
    float oacc[4][8];
    #pragma unroll
    for (int i = 0; i < 4; i++)
        #pragma unroll
        for (int j = 0; j < 8; j++) oacc[i][j] = 0.f;

    for (int tile = 0; tile < 17; tile++) {
        int kstart = q0 - WINSZ + tile * ATT_NK;
        if (kstart + ATT_NK - 1 < 0) continue;

        __syncthreads();
        for (int u = tid; u < 64*32; u += 256) {
            int r  = u >> 5;
            int cs = (u & 31) * 4;
            int g = kstart + r;
            float4 kk = make_float4(0.f,0.f,0.f,0.f);
            float4 vv = make_float4(0.f,0.f,0.f,0.f);
            if (g >= 0) {
                const float* base = kv + (size_t)(b*Tdim + g) * (2*HD);
                kk = *(const float4*)(base + cs);
                vv = *(const float4*)(base + HD + cs);
            }
            sK[(cs+0)*68 + r] = kk.x;
            sK[(cs+1)*68 + r] = kk.y;
            sK[(cs+2)*68 + r] = kk.z;
            sK[(cs+3)*68 + r] = kk.w;
            *(float4*)&sV[r*132 + cs] = vv;
        }
        __syncthreads();

        {
            float sacc[4][4];
            #pragma unroll
            for (int i = 0; i < 4; i++)
                #pragma unroll
                for (int j = 0; j < 4; j++) sacc[i][j] = 0.f;
            #pragma unroll 8
            for (int kk = 0; kk < HD; kk++) {
                float4 aq = *(const float4*)&sQ[kk*68 + tys*4];
                float4 bk = *(const float4*)&sK[kk*68 + txs*4];
                float a[4] = {aq.x, aq.y, aq.z, aq.w};
                float bb[4] = {bk.x, bk.y, bk.z, bk.w};
                #pragma unroll
                for (int i = 0; i < 4; i++)
                    #pragma unroll
                    for (int j = 0; j < 4; j++)
                        sacc[i][j] = fmaf(a[i], bb[j], sacc[i][j]);
            }
            #pragma unroll
            for (int i = 0; i < 4; i++) {
                int r = tys*4 + i;
                int t = q0 + r;
                #pragma unroll
                for (int j = 0; j < 4; j++) {
                    int g = kstart + txs*4 + j;
                    float s = sacc[i][j] * 0.088388347648318447f;
                    bool valid = (g >= 0) && (g <= t) && (g >= t - WINSZ);
                    sP[(txs*4 + j)*68 + r] = valid ? s : -1e30f;
                }
            }
        }
        __syncthreads();

        if (tid < 64) {
            int r = tid;
            float m_old = rowm[r];
            float mx = m_old;
            #pragma unroll 8
            for (int j = 0; j < 64; j++) mx = fmaxf(mx, sP[j*68 + r]);
            float sum = 0.f;
            #pragma unroll 8
            for (int j = 0; j < 64; j++) {
                float p = expf(sP[j*68 + r] - mx);
                sP[j*68 + r] = p;
                sum += p;
            }
            float sc = expf(m_old - mx);
            rowl[r] = rowl[r] * sc + sum;
            rowm[r] = mx;
            rowsc[r] = sc;
        }
        __syncthreads();

        #pragma unroll
        for (int i = 0; i < 4; i++) {
            float sc = rowsc[tys*4 + i];
            #pragma unroll
            for (int j = 0; j < 8; j++) oacc[i][j] *= sc;
        }
        #pragma unroll 4
        for (int j = 0; j < ATT_NK; j++) {
            float4 pa = *(const float4*)&sP[j*68 + tys*4];
            float4 v0 = *(const float4*)&sV[j*132 + txs*8];
            float4 v1 = *(const float4*)&sV[j*132 + txs*8 + 4];
            float pr[4] = {pa.x, pa.y, pa.z, pa.w};
            float vb[8] = {v0.x, v0.y, v0.z, v0.w, v1.x, v1.y, v1.z, v1.w};
            #pragma unroll
            for (int i = 0; i < 4; i++)
                #pragma unroll
                for (int d = 0; d < 8; d++)
                    oacc[i][d] = fmaf(pr[i], vb[d], oacc[i][d]);
        }
    }

    #pragma unroll
    for (int i = 0; i < 4; i++) {
        int r = tys*4 + i;
        float invl = 1.0f / rowl[r];
        size_t ob = (size_t)(b*Tdim + q0 + r)*(QH*HD) + h*HD + txs*8;
        #pragma unroll
        for (int d = 0; d < 8; d++) {
            float y = oacc[i][d] * invl;
            __nv_bfloat16 hh, ll; split_bf16(y, hh, ll);
            ohi[ob + d] = hh;
            olo[ob + d] = ll;
        }
    }
}

// ---------------------------------------------------------------------------
// launch
// ---------------------------------------------------------------------------
static void bgemm(const __nv_bfloat16* Ahi, const __nv_bfloat16* Alo,
                  const __nv_bfloat16* Whi, const __nv_bfloat16* Wlo,
                  const float* bias, const float* res, float* C, int N, int K) {
    dim3 grid(N / CTN, MROWS / CTM);
    if (bias) {
        bgemm_kernel<true,false><<<grid, 256, GEMM_SMEM_BYTES>>>(Ahi, Alo, Whi, Wlo, bias, res, C, N, K);
    } else if (res) {
        bgemm_kernel<false,true><<<grid, 256, GEMM_SMEM_BYTES>>>(Ahi, Alo, Whi, Wlo, bias, res, C, N, K);
    } else {
        bgemm_kernel<false,false><<<grid, 256, GEMM_SMEM_BYTES>>>(Ahi, Alo, Whi, Wlo, bias, res, C, N, K);
    }
}

extern "C" void kernel_launch(void* const* d_in, const int* in_sizes, int n_in,
                              void* d_out, int out_size) {
    const float* x         = (const float*)d_in[0];
    const float* gn_hawk   = (const float*)d_in[1];
    const float* gn_hgmlp  = (const float*)d_in[2];
    const float* gn_smqa   = (const float*)d_in[3];
    const float* gn_sgmlp  = (const float*)d_in[4];
    const float* hawk_Win  = (const float*)d_in[5];
    const float* hawk_cw   = (const float*)d_in[6];
    const float* hawk_cb   = (const float*)d_in[7];
    const float* hawk_Wg   = (const float*)d_in[8];
    const float* hawk_bg   = (const float*)d_in[9];
    const float* hawk_fb   = (const float*)d_in[10];
    const float* hawk_Wout = (const float*)d_in[11];
    const float* g1_Wgrow  = (const float*)d_in[12];
    const float* g1_Wshr   = (const float*)d_in[13];
    const float* g2_Wgrow  = (const float*)d_in[14];
    const float* g2_Wshr   = (const float*)d_in[15];
    const float* smqa_Wq   = (const float*)d_in[16];
    const float* smqa_Wkv  = (const float*)d_in[17];
    const float* smqa_Wout = (const float*)d_in[18];
    float* out = (float*)d_out;

    float *big, *mid, *small;
    __nv_bfloat16 *Ahi, *Alo, *Whi, *Wlo;
    cudaGetSymbolAddress((void**)&big,   g_big);
    cudaGetSymbolAddress((void**)&mid,   g_mid);
    cudaGetSymbolAddress((void**)&small, g_small);
    cudaGetSymbolAddress((void**)&Ahi,   g_Ahi);
    cudaGetSymbolAddress((void**)&Alo,   g_Alo);
    cudaGetSymbolAddress((void**)&Whi,   g_Whi);
    cudaGetSymbolAddress((void**)&Wlo,   g_Wlo);

    static const size_t ATT_SMEM_BYTES = ATT_SMEM_FLOATS * sizeof(float);
    cudaFuncSetAttribute((const void*)attn_kernel,
                         cudaFuncAttributeMaxDynamicSharedMemorySize,
                         (int)ATT_SMEM_BYTES);
    cudaFuncSetAttribute((const void*)bgemm_kernel<true,false>,
                         cudaFuncAttributeMaxDynamicSharedMemorySize, GEMM_SMEM_BYTES);
    cudaFuncSetAttribute((const void*)bgemm_kernel<false,true>,
                         cudaFuncAttributeMaxDynamicSharedMemorySize, GEMM_SMEM_BYTES);
    cudaFuncSetAttribute((const void*)bgemm_kernel<false,false>,
                         cudaFuncAttributeMaxDynamicSharedMemorySize, GEMM_SMEM_BYTES);

    const int EW = 256;
    #define CONVW(W, n) convw_kernel<<<((n)/4 + EW - 1)/EW, EW>>>((W), Whi, Wlo, (n)/4)

    // ---------------- stage 1: hawk ----------------
    rmsnorm_bf16_kernel<<<MROWS, 256>>>(x, gn_hawk, Ahi, Alo);
    CONVW(hawk_Win, 2*HID*DIM);
    bgemm(Ahi, Alo, Whi, Wlo, nullptr, nullptr, big, 2*HID, DIM);           // gh
    conv_kernel<<<(MROWS*HID)/EW, EW>>>(big, hawk_cw, hawk_cb, small, Ahi, Alo);
    CONVW(hawk_Wg, 2*HID*HID);
    bgemm(Ahi, Alo, Whi, Wlo, hawk_bg, nullptr, mid, 2*HID, HID);           // gi
    gates_kernel<<<(MROWS*HID)/EW, EW>>>(mid, small, hawk_fb);
    scan_kernel<<<(Bdim*HID + EW - 1)/EW, EW>>>(mid, big, Ahi, Alo);        // hy -> bf16
    CONVW(hawk_Wout, DIM*HID);
    bgemm(Ahi, Alo, Whi, Wlo, nullptr, x, out, DIM, HID);                   // out = x + hy@Wout^T

    // ---------------- stage 2: gated MLP 1 ----------------
    rmsnorm_bf16_kernel<<<MROWS, 256>>>(out, gn_hgmlp, Ahi, Alo);
    CONVW(g1_Wgrow, 2*GH*DIM);
    bgemm(Ahi, Alo, Whi, Wlo, nullptr, nullptr, big, 2*GH, DIM);
    gelugate_kernel<<<(MROWS*GH)/EW, EW>>>(big, Ahi, Alo);
    CONVW(g1_Wshr, DIM*GH);
    bgemm(Ahi, Alo, Whi, Wlo, nullptr, out, out, DIM, GH);

    // ---------------- stage 3: sliding-window MQA ----------------
    rmsnorm_bf16_kernel<<<MROWS, 256>>>(out, gn_smqa, Ahi, Alo);
    float* qb  = big;
    float* kvb = big + (size_t)MROWS * (QH*HD);
    CONVW(smqa_Wq, QH*HD*DIM);
    bgemm(Ahi, Alo, Whi, Wlo, nullptr, nullptr, qb, QH*HD, DIM);
    CONVW(smqa_Wkv, 2*HD*DIM);
    bgemm(Ahi, Alo, Whi, Wlo, nullptr, nullptr, kvb, 2*HD, DIM);
    {
        int total = MROWS*QH*(HD/2) + MROWS*(HD/2);
        rotary_kernel<<<(total + EW - 1)/EW, EW>>>(qb, kvb);
    }
    attn_kernel<<<dim3(Tdim/ATT_MQ, QH, Bdim), 256, ATT_SMEM_BYTES>>>(qb, kvb, Ahi, Alo);
    CONVW(smqa_Wout, DIM*DIM);
    bgemm(Ahi, Alo, Whi, Wlo, nullptr, out, out, DIM, DIM);

    // ---------------- stage 4: gated MLP 2 ----------------
    rmsnorm_bf16_kernel<<<MROWS, 256>>>(out, gn_sgmlp, Ahi, Alo);
    CONVW(g2_Wgrow, 2*GH*DIM);
    bgemm(Ahi, Alo, Whi, Wlo, nullptr, nullptr, big, 2*GH, DIM);
    gelugate_kernel<<<(MROWS*GH)/EW, EW>>>(big, Ahi, Alo);
    CONVW(g2_Wshr, DIM*GH);
    bgemm(Ahi, Alo, Whi, Wlo, nullptr, out, out, DIM, GH);
    #undef CONVW
}

// round 5
// speedup vs baseline: 3.0174x; 1.4422x over previous
#include <cuda_runtime.h>
#include <cuda_bf16.h>
#include <math.h>
#include <stdint.h>

// ---------------------------------------------------------------------------
// GriffinBlock: HMMA bf16x3 GEMMs + HMMA bf16x3 flash attention + parallel scan
// B=4, T=2048, DIM=1024, HID=1536, GH=2048, K=4, HD=128, QH=8, W=1024
// ---------------------------------------------------------------------------

#define Bdim 4
#define Tdim 2048
#define DIM 1024
#define HID 1536
#define GH  2048
#define KCONV 4
#define HD  128
#define QH  8
#define WINSZ 1024
#define MROWS (Bdim*Tdim)   // 8192
#define LOG2E 1.4426950408889634f

// ---------------- static scratch ----------------
__device__ float g_big[33554432];      // 8192*4096
__device__ float g_mid[25165824];      // 8192*3072 (hawk gi; attn bf16 q/k/v scratch)
__device__ float g_small[12582912];    // 8192*1536
__device__ __nv_bfloat16 g_Ahi[16777216];  // 8192*2048 max
__device__ __nv_bfloat16 g_Alo[16777216];
__device__ __nv_bfloat16 g_Whi[4718592];   // 3072*1536 max
__device__ __nv_bfloat16 g_Wlo[4718592];
__device__ float g_chA[98304];
__device__ float g_chS[98304];
__device__ float g_sIn[98304];

__device__ __forceinline__ float gelu_exact(float x) {
    return 0.5f * x * (1.0f + erff(x * 0.70710678118654752f));
}
__device__ __forceinline__ float sigmoidf_(float x) {
    return 1.0f / (1.0f + expf(-x));
}
__device__ __forceinline__ void split_bf16(float v, __nv_bfloat16& h, __nv_bfloat16& l) {
    h = __float2bfloat16(v);
    l = __float2bfloat16(v - __bfloat162float(h));
}

__device__ __forceinline__ uint32_t smem_u32(const void* p) {
    uint32_t a;
    asm("{ .reg .u64 t; cvta.to.shared.u64 t, %1; cvt.u32.u64 %0, t; }" : "=r"(a) : "l"(p));
    return a;
}
__device__ __forceinline__ void cp16(uint32_t dst, const void* src) {
    asm volatile("cp.async.ca.shared.global [%0], [%1], 16;" :: "r"(dst), "l"(src));
}

#define LDSM4(r0, r1, r2, r3, addr) \
    asm volatile("ldmatrix.sync.aligned.m8n8.x4.shared.b16 {%0,%1,%2,%3}, [%4];" \
        : "=r"(r0), "=r"(r1), "=r"(r2), "=r"(r3) : "r"(addr))

#define MMA_BF16(d, a, b) \
    asm volatile("mma.sync.aligned.m16n8k16.row.col.f32.bf16.bf16.f32 " \
        "{%0,%1,%2,%3}, {%4,%5,%6,%7}, {%8,%9}, {%0,%1,%2,%3};" \
        : "+f"((d)[0]), "+f"((d)[1]), "+f"((d)[2]), "+f"((d)[3]) \
        : "r"((a)[0]), "r"((a)[1]), "r"((a)[2]), "r"((a)[3]), \
          "r"((b)[0]), "r"((b)[1]))

// ---------------------------------------------------------------------------
// bf16x3 HMMA GEMM (unchanged from R4): C = (Ahi+Alo)(Whi+Wlo)^T (+bias)(+res)
// ---------------------------------------------------------------------------
#define CTM 128
#define CTN 128
#define CTK 64
#define APITCH 72
#define OFF_SALO_B 18432u
#define OFF_SBHI_B 36864u
#define OFF_SBLO_B 55296u
#define STAGE_BYTES 73728u
#define GEMM_SMEM_BYTES (2u*STAGE_BYTES)

template<bool HAS_BIAS, bool HAS_RES>
__global__ void __launch_bounds__(256, 1)
bgemm_kernel(const __nv_bfloat16* __restrict__ Ahi, const __nv_bfloat16* __restrict__ Alo,
             const __nv_bfloat16* __restrict__ Whi, const __nv_bfloat16* __restrict__ Wlo,
             const float* __restrict__ bias, const float* __restrict__ res,
             float* __restrict__ C, int N, int K) {
    extern __shared__ char smc[];
    const uint32_t sb = smem_u32(smc);
    const int tid = threadIdx.x;
    const int lane = tid & 31;
    const int wid = tid >> 5;
    const int wy = wid & 3;
    const int wx = wid >> 2;
    const int m0 = blockIdx.y * CTM;
    const int n0 = blockIdx.x * CTN;

    const int arow = wy*32 + (lane & 15);
    const int acol = (lane >> 4) * 8;
    const uint32_t aoff = (uint32_t)(arow*APITCH + acol) * 2u;
    const int g  = lane >> 3;
    const int rr = lane & 7;
    const int brow = wx*64 + rr + ((g >> 1) << 3);
    const int bcol = (g & 1) * 8;
    const uint32_t boff = (uint32_t)(brow*APITCH + bcol) * 2u;

    float acc[2][8][4];
    #pragma unroll
    for (int i = 0; i < 2; i++)
        #pragma unroll
        for (int j = 0; j < 8; j++)
            #pragma unroll
            for (int v = 0; v < 4; v++) acc[i][j][v] = 0.f;

    const int NC = K / CTK;

    #define LOAD_STAGE(stg, kb) do { \
        uint32_t sbase_ = sb + (stg)*STAGE_BYTES; \
        _Pragma("unroll") \
        for (int it_ = 0; it_ < 4; it_++) { \
            int u_ = tid + it_*256; \
            int r_ = u_ >> 3; \
            int c_ = u_ & 7; \
            uint32_t d_ = sbase_ + (uint32_t)r_*144u + (uint32_t)c_*16u; \
            size_t ga_ = (size_t)(m0 + r_) * K + (kb) + c_*8; \
            size_t gb_ = (size_t)(n0 + r_) * K + (kb) + c_*8; \
            cp16(d_,              Ahi + ga_); \
            cp16(d_ + OFF_SALO_B, Alo + ga_); \
            cp16(d_ + OFF_SBHI_B, Whi + gb_); \
            cp16(d_ + OFF_SBLO_B, Wlo + gb_); \
        } \
        asm volatile("cp.async.commit_group;"); \
    } while (0)

    LOAD_STAGE(0, 0);

    for (int ch = 0; ch < NC; ch++) {
        const int stg = ch & 1;
        if (ch + 1 < NC) {
            LOAD_STAGE(stg ^ 1, (ch + 1) * CTK);
            asm volatile("cp.async.wait_group 1;");
        } else {
            asm volatile("cp.async.wait_group 0;");
        }
        __syncthreads();

        const uint32_t sbase = sb + stg * STAGE_BYTES;
        #pragma unroll
        for (int k16 = 0; k16 < 4; k16++) {
            uint32_t ah[2][4], al[2][4], bh[8][2], bl[8][2];
            #pragma unroll
            for (int mt = 0; mt < 2; mt++) {
                uint32_t ad = sbase + aoff + (uint32_t)mt*(16*APITCH*2) + (uint32_t)k16*32u;
                LDSM4(ah[mt][0], ah[mt][1], ah[mt][2], ah[mt][3], ad);
                LDSM4(al[mt][0], al[mt][1], al[mt][2], al[mt][3], ad + OFF_SALO_B);
            }
            #pragma unroll
            for (int jp = 0; jp < 4; jp++) {
                uint32_t bd = sbase + boff + (uint32_t)jp*(16*APITCH*2) + (uint32_t)k16*32u;
                LDSM4(bh[2*jp][0], bh[2*jp][1], bh[2*jp+1][0], bh[2*jp+1][1], bd + OFF_SBHI_B);
                LDSM4(bl[2*jp][0], bl[2*jp][1], bl[2*jp+1][0], bl[2*jp+1][1], bd + OFF_SBLO_B);
            }
            #pragma unroll
            for (int mt = 0; mt < 2; mt++)
                #pragma unroll
                for (int j = 0; j < 8; j++) {
                    MMA_BF16(acc[mt][j], ah[mt], bh[j]);
                    MMA_BF16(acc[mt][j], ah[mt], bl[j]);
                    MMA_BF16(acc[mt][j], al[mt], bh[j]);
                }
        }
        __syncthreads();
    }
    #undef LOAD_STAGE

    const int rbase = m0 + wy*32 + (lane >> 2);
    const int cbase = n0 + wx*64 + (lane & 3)*2;
    #pragma unroll
    for (int mt = 0; mt < 2; mt++) {
        #pragma unroll
        for (int half = 0; half < 2; half++) {
            const int row = rbase + mt*16 + half*8;
            #pragma unroll
            for (int j = 0; j < 8; j++) {
                const int col = cbase + j*8;
                float v0 = acc[mt][j][half*2 + 0];
                float v1 = acc[mt][j][half*2 + 1];
                if (HAS_BIAS) { v0 += bias[col]; v1 += bias[col + 1]; }
                if (HAS_RES) {
                    const float2 rv = *(const float2*)(res + (size_t)row * N + col);
                    v0 += rv.x; v1 += rv.y;
                }
                float2 o; o.x = v0; o.y = v1;
                *(float2*)(C + (size_t)row * N + col) = o;
            }
        }
    }
}

// ---------------------------------------------------------------------------
// weight fp32 -> bf16 hi/lo
// ---------------------------------------------------------------------------
__global__ void convw_kernel(const float* __restrict__ s,
                             __nv_bfloat16* __restrict__ hi,
                             __nv_bfloat16* __restrict__ lo, int n4) {
    int i = blockIdx.x * blockDim.x + threadIdx.x;
    if (i >= n4) return;
    float4 v = ((const float4*)s)[i];
    __nv_bfloat16 h0, h1, h2, h3, l0, l1, l2, l3;
    split_bf16(v.x, h0, l0); split_bf16(v.y, h1, l1);
    split_bf16(v.z, h2, l2); split_bf16(v.w, h3, l3);
    __nv_bfloat162* hp = (__nv_bfloat162*)hi;
    __nv_bfloat162* lp = (__nv_bfloat162*)lo;
    hp[2*i]   = __nv_bfloat162(h0, h1);
    hp[2*i+1] = __nv_bfloat162(h2, h3);
    lp[2*i]   = __nv_bfloat162(l0, l1);
    lp[2*i+1] = __nv_bfloat162(l2, l3);
}

// ---------------------------------------------------------------------------
// RMSNorm -> bf16 hi/lo
// ---------------------------------------------------------------------------
__global__ void rmsnorm_bf16_kernel(const float* __restrict__ x,
                                    const float* __restrict__ gamma,
                                    __nv_bfloat16* __restrict__ hi,
                                    __nv_bfloat16* __restrict__ lo) {
    int row = blockIdx.x;
    int tid = threadIdx.x;
    float4 v = ((const float4*)(x + (size_t)row * DIM))[tid];
    float ss = v.x*v.x + v.y*v.y + v.z*v.z + v.w*v.w;
    #pragma unroll
    for (int o = 16; o; o >>= 1) ss += __shfl_xor_sync(0xffffffffu, ss, o);
    __shared__ float red[8];
    __shared__ float stot;
    if ((tid & 31) == 0) red[tid >> 5] = ss;
    __syncthreads();
    if (tid == 0) {
        float s = 0.f;
        #pragma unroll
        for (int i = 0; i < 8; i++) s += red[i];
        stot = s;
    }
    __syncthreads();
    float scale = 32.0f * rsqrtf(stot);
    float4 g = ((const float4*)gamma)[tid];
    float o0 = v.x*scale*g.x, o1 = v.y*scale*g.y, o2 = v.z*scale*g.z, o3 = v.w*scale*g.w;
    __nv_bfloat16 h0,h1,h2,h3,l0,l1,l2,l3;
    split_bf16(o0,h0,l0); split_bf16(o1,h1,l1); split_bf16(o2,h2,l2); split_bf16(o3,h3,l3);
    __nv_bfloat162* hp = (__nv_bfloat162*)(hi + (size_t)row * DIM);
    __nv_bfloat162* lp = (__nv_bfloat162*)(lo + (size_t)row * DIM);
    hp[2*tid]   = __nv_bfloat162(h0,h1);
    hp[2*tid+1] = __nv_bfloat162(h2,h3);
    lp[2*tid]   = __nv_bfloat162(l0,l1);
    lp[2*tid+1] = __nv_bfloat162(l2,l3);
}

// ---------------------------------------------------------------------------
// hawk depthwise causal conv (K=4): fp32 out + bf16 hi/lo out
// ---------------------------------------------------------------------------
__global__ void conv_kernel(const float* __restrict__ gh,
                            const float* __restrict__ cw,
                            const float* __restrict__ cb,
                            float* __restrict__ hconv,
                            __nv_bfloat16* __restrict__ hi,
                            __nv_bfloat16* __restrict__ lo) {
    int idx = blockIdx.x * blockDim.x + threadIdx.x;
    if (idx >= MROWS * HID) return;
    int c = idx % HID;
    int bt = idx / HID;
    int t = bt & (Tdim - 1);
    int b = bt >> 11;
    float acc = cb[c];
    #pragma unroll
    for (int k = 0; k < KCONV; k++) {
        int tt = t - (KCONV - 1) + k;
        if (tt >= 0)
            acc += cw[c*KCONV + k] * gh[(size_t)(b*Tdim + tt) * (2*HID) + HID + c];
    }
    hconv[(size_t)bt * HID + c] = acc;
    __nv_bfloat16 h, l; split_bf16(acc, h, l);
    hi[(size_t)bt * HID + c] = h;
    lo[(size_t)bt * HID + c] = l;
}

// ---------------------------------------------------------------------------
// gates: gi[bt][3072] = [forget|inp] -> [alpha|xs] in place
// ---------------------------------------------------------------------------
__global__ void gates_kernel(float* __restrict__ gi,
                             const float* __restrict__ hconv,
                             const float* __restrict__ fb) {
    int idx = blockIdx.x * blockDim.x + threadIdx.x;
    if (idx >= MROWS * HID) return;
    int c = idx % HID;
    size_t bt = idx / HID;
    float f  = gi[bt * (2*HID) + c];
    float ip = gi[bt * (2*HID) + HID + c];
    float h  = hconv[bt * HID + c];
    float sp = log1pf(expf(fb[c]));
    float alpha = expf(-8.0f * sp * sigmoidf_(f));
    float beta  = sqrtf(1.0f - alpha*alpha + 1e-6f);
    gi[bt * (2*HID) + c]       = alpha;
    gi[bt * (2*HID) + HID + c] = beta * sigmoidf_(ip) * h;
}

// ---------------------------------------------------------------------------
// chunked parallel scan (3 phases), chunk = 128 steps, 16 chunks
// ---------------------------------------------------------------------------
#define SCH 128
#define NCH 16
__global__ void scanA_kernel(const float* __restrict__ gi,
                             float* __restrict__ chA, float* __restrict__ chS) {
    int idx = blockIdx.x * blockDim.x + threadIdx.x;
    if (idx >= Bdim * NCH * HID) return;
    int c = idx % HID;
    int r = idx / HID;
    int ch = r & (NCH - 1);
    int b  = r >> 4;
    size_t base = ((size_t)b * Tdim + ch * SCH) * (2*HID) + c;
    float ap = 1.f, s = 0.f;
    for (int t = 0; t < SCH; t++) {
        float a = gi[base + (size_t)t * (2*HID)];
        float x = gi[base + (size_t)t * (2*HID) + HID];
        s = fmaf(a, s, x);
        ap *= a;
    }
    chA[idx] = ap;
    chS[idx] = s;
}
__global__ void scanB_kernel(const float* __restrict__ chA, const float* __restrict__ chS,
                             float* __restrict__ sIn) {
    int idx = blockIdx.x * blockDim.x + threadIdx.x;
    if (idx >= Bdim * HID) return;
    int c = idx % HID;
    int b = idx / HID;
    float s = 0.f;
    #pragma unroll
    for (int ch = 0; ch < NCH; ch++) {
        size_t o = ((size_t)(b * NCH + ch)) * HID + c;
        sIn[o] = s;
        s = fmaf(chA[o], s, chS[o]);
    }
}
__global__ void scanC_kernel(const float* __restrict__ gi, const float* __restrict__ gh,
                             const float* __restrict__ sIn,
                             __nv_bfloat16* __restrict__ hi, __nv_bfloat16* __restrict__ lo) {
    int idx = blockIdx.x * blockDim.x + threadIdx.x;
    if (idx >= Bdim * NCH * HID) return;
    int c = idx % HID;
    int r = idx / HID;
    int ch = r & (NCH - 1);
    int b  = r >> 4;
    float st = sIn[idx];
    size_t base = ((size_t)b * Tdim + ch * SCH) * (2*HID) + c;
    size_t ob   = ((size_t)b * Tdim + ch * SCH) * HID + c;
    for (int t = 0; t < SCH; t++) {
        size_t o = base + (size_t)t * (2*HID);
        float a = gi[o];
        float x = gi[o + HID];
        float g = gh[o];
        st = fmaf(a, st, x);
        float y = gelu_exact(g) * st;
        __nv_bfloat16 h, l; split_bf16(y, h, l);
        hi[ob + (size_t)t * HID] = h;
        lo[ob + (size_t)t * HID] = l;
    }
}

// ---------------------------------------------------------------------------
// gated-MLP activation -> bf16 hi/lo
// ---------------------------------------------------------------------------
__global__ void gelugate_kernel(const float* __restrict__ grow,
                                __nv_bfloat16* __restrict__ hi,
                                __nv_bfloat16* __restrict__ lo) {
    int idx = blockIdx.x * blockDim.x + threadIdx.x;
    if (idx >= MROWS * GH) return;
    int c  = idx & (GH - 1);
    size_t bt = idx >> 11;
    float g = grow[bt * (2*GH) + c];
    float h = grow[bt * (2*GH) + GH + c];
    float y = gelu_exact(g) * h;
    __nv_bfloat16 hh, ll; split_bf16(y, hh, ll);
    hi[idx] = hh;
    lo[idx] = ll;
}

// ---------------------------------------------------------------------------
// rotary + 1/sqrt(HD) q-scale + bf16 hi/lo split + V transpose
// outputs: qhi/qlo [b][h][t][d], khi/klo [b][t][d], vthi/vtlo [b][d][t]
// ---------------------------------------------------------------------------
__global__ void rotsplit_kernel(const float* __restrict__ qb, const float* __restrict__ kvb,
                                __nv_bfloat16* __restrict__ qhi, __nv_bfloat16* __restrict__ qlo,
                                __nv_bfloat16* __restrict__ khi, __nv_bfloat16* __restrict__ klo,
                                __nv_bfloat16* __restrict__ vthi, __nv_bfloat16* __restrict__ vtlo) {
    const int NQp = MROWS * QH * (HD/2);
    const int NKp = MROWS * (HD/2);
    const int NV  = MROWS * HD;
    int idx = blockIdx.x * blockDim.x + threadIdx.x;
    if (idx < NQp) {
        int i  = idx & 63;
        int r  = idx >> 6;
        int hh = r & 7;
        int bt = r >> 3;
        int t = bt & (Tdim - 1);
        int b = bt >> 11;
        const float* p = qb + (size_t)bt * (QH*HD) + hh*HD + 2*i;
        float inv = expf(-(float)(2*i) * (9.210340371976184f / 128.0f));
        float ang = (float)t * inv;
        float sn, cs; sincosf(ang, &sn, &cs);
        float x0 = p[0], x1 = p[1];
        float y0 = (x0*cs - x1*sn) * 0.088388347648318447f;
        float y1 = (x1*cs + x0*sn) * 0.088388347648318447f;
        __nv_bfloat16 h0,l0,h1,l1;
        split_bf16(y0,h0,l0); split_bf16(y1,h1,l1);
        size_t o = (((size_t)(b*QH + hh)) * Tdim + t) * HD + 2*i;
        *(__nv_bfloat162*)(qhi + o) = __nv_bfloat162(h0,h1);
        *(__nv_bfloat162*)(qlo + o) = __nv_bfloat162(l0,l1);
    } else if (idx < NQp + NKp) {
        int j = idx - NQp;
        int i = j & 63;
        int bt = j >> 6;
        int t = bt & (Tdim - 1);
        const float* p = kvb + (size_t)bt * (2*HD) + 2*i;
        float inv = expf(-(float)(2*i) * (9.210340371976184f / 128.0f));
        float ang = (float)t * inv;
        float sn, cs; sincosf(ang, &sn, &cs);
        float x0 = p[0], x1 = p[1];
        float y0 = x0*cs - x1*sn;
        float y1 = x1*cs + x0*sn;
        __nv_bfloat16 h0,l0,h1,l1;
        split_bf16(y0,h0,l0); split_bf16(y1,h1,l1);
        size_t o = (size_t)bt * HD + 2*i;
        *(__nv_bfloat162*)(khi + o) = __nv_bfloat162(h0,h1);
        *(__nv_bfloat162*)(klo + o) = __nv_bfloat162(l0,l1);
    } else if (idx < NQp + NKp + NV) {
        int j = idx - NQp - NKp;   // j = (b*HD + d)*Tdim + t
        int t = j & (Tdim - 1);
        int d = (j >> 11) & (HD - 1);
        int b = j >> 18;
        float v = kvb[((size_t)(b*Tdim + t)) * (2*HD) + HD + d];
        __nv_bfloat16 h, l; split_bf16(v, h, l);
        vthi[j] = h;
        vtlo[j] = l;
    }
}

// ---------------------------------------------------------------------------
// HMMA flash attention: 128 q rows/block, 64-key tiles, bf16x3 QK and PV.
// 8 warps; warp w owns q rows [w*16, w*16+16). FA2 register softmax.
// ---------------------------------------------------------------------------
#define AQ 128
#define AQH_OFF 0u
#define AQL_OFF 34816u
#define AST_OFF 69632u
#define AKH 0u
#define AKL 17408u
#define AVH 34816u
#define AVL 53248u
#define ASTAGE 71680u
#define ATT_SMEM (69632u + 2u*71680u)   // 212992

__global__ void __launch_bounds__(256, 1)
attn_hmma_kernel(const __nv_bfloat16* __restrict__ qhi, const __nv_bfloat16* __restrict__ qlo,
                 const __nv_bfloat16* __restrict__ khi, const __nv_bfloat16* __restrict__ klo,
                 const __nv_bfloat16* __restrict__ vthi, const __nv_bfloat16* __restrict__ vtlo,
                 __nv_bfloat16* __restrict__ ohi, __nv_bfloat16* __restrict__ olo) {
    extern __shared__ char smc[];
    const uint32_t sb = smem_u32(smc);
    const int tid  = threadIdx.x;
    const int lane = tid & 31;
    const int w    = tid >> 5;
    const int b  = blockIdx.z;
    const int h  = blockIdx.y;
    const int q0 = blockIdx.x * AQ;

    // Q tile -> smem (group 0)
    {
        const __nv_bfloat16* qh_ = qhi + ((size_t)(b*QH + h) * Tdim + q0) * HD;
        const __nv_bfloat16* ql_ = qlo + ((size_t)(b*QH + h) * Tdim + q0) * HD;
        #pragma unroll
        for (int it = 0; it < 8; it++) {
            int u = tid + it*256;
            int r = u >> 4, c = u & 15;
            uint32_t d = sb + AQH_OFF + (uint32_t)r*272u + (uint32_t)c*16u;
            cp16(d,           qh_ + (size_t)r*HD + c*8);
            cp16(d + AQL_OFF, ql_ + (size_t)r*HD + c*8);
        }
        asm volatile("cp.async.commit_group;");
    }

    const int ks0 = (q0 >= WINSZ) ? (q0 - WINSZ) : 0;
    const int nt  = (q0 + AQ - ks0) >> 6;

    #define LOAD_KV(stg, ks) do { \
        uint32_t sbase_ = sb + AST_OFF + (uint32_t)(stg)*ASTAGE; \
        const __nv_bfloat16* kh_ = khi + ((size_t)b*Tdim + (ks))*HD; \
        const __nv_bfloat16* kl_ = klo + ((size_t)b*Tdim + (ks))*HD; \
        const __nv_bfloat16* vh_ = vthi + (size_t)b*HD*Tdim + (ks); \
        const __nv_bfloat16* vl_ = vtlo + (size_t)b*HD*Tdim + (ks); \
        _Pragma("unroll") \
        for (int it_ = 0; it_ < 4; it_++) { \
            int u_ = tid + it_*256; \
            int r_ = u_ >> 4, c_ = u_ & 15; \
            uint32_t d_ = sbase_ + AKH + (uint32_t)r_*272u + (uint32_t)c_*16u; \
            cp16(d_,             kh_ + (size_t)r_*HD + c_*8); \
            cp16(d_ + (AKL-AKH), kl_ + (size_t)r_*HD + c_*8); \
            int r2_ = u_ >> 3, c2_ = u_ & 7; \
            uint32_t d2_ = sbase_ + AVH + (uint32_t)r2_*144u + (uint32_t)c2_*16u; \
            cp16(d2_,            vh_ + (size_t)r2_*Tdim + c2_*8); \
            cp16(d2_ + (AVL-AVH), vl_ + (size_t)r2_*Tdim + c2_*8); \
        } \
        asm volatile("cp.async.commit_group;"); \
    } while (0)

    LOAD_KV(0, ks0);
    asm volatile("cp.async.wait_group 1;");   // Q complete
    __syncthreads();

    // Q fragments (persistent)
    uint32_t qfh[8][4], qfl[8][4];
    {
        const int arow = w*16 + (lane & 15);
        const int acol = (lane >> 4) * 8;
        uint32_t abase = sb + AQH_OFF + (uint32_t)(arow*136 + acol)*2u;
        #pragma unroll
        for (int k = 0; k < 8; k++) {
            LDSM4(qfh[k][0],qfh[k][1],qfh[k][2],qfh[k][3], abase + (uint32_t)k*32u);
            LDSM4(qfl[k][0],qfl[k][1],qfl[k][2],qfl[k][3], abase + AQL_OFF + (uint32_t)k*32u);
        }
    }

    float o_[16][4];
    #pragma unroll
    for (int j = 0; j < 16; j++)
        #pragma unroll
        for (int v = 0; v < 4; v++) o_[j][v] = 0.f;
    float m0 = -1e30f, m1 = -1e30f, l0 = 0.f, l1 = 0.f;

    const int t0 = q0 + w*16 + (lane >> 2);
    const int t1 = t0 + 8;
    const int cb2 = (lane & 3)*2;
    const int gB  = lane >> 3;
    const int rrB = lane & 7;
    const int browB = rrB + ((gB >> 1) << 3);
    const int bcolB = (gB & 1) * 8;

    for (int i = 0; i < nt; i++) {
        const int stg = i & 1;
        if (i + 1 < nt) {
            LOAD_KV(stg ^ 1, ks0 + (i+1)*64);
            asm volatile("cp.async.wait_group 1;");
        } else {
            asm volatile("cp.async.wait_group 0;");
        }
        __syncthreads();
        const uint32_t kb_ = sb + AST_OFF + (uint32_t)stg*ASTAGE;
        const int ks = ks0 + i*64;

        // ---- S = Q K^T (bf16x3) ----
        float s_[8][4];
        #pragma unroll
        for (int j = 0; j < 8; j++)
            #pragma unroll
            for (int v = 0; v < 4; v++) s_[j][v] = 0.f;
        #pragma unroll
        for (int jp = 0; jp < 4; jp++) {
            #pragma unroll
            for (int k = 0; k < 8; k++) {
                uint32_t ad = kb_ + AKH + (uint32_t)((browB + jp*16)*136 + bcolB + k*16)*2u;
                uint32_t bh0,bh1,bh2,bh3, bl0,bl1,bl2,bl3;
                LDSM4(bh0,bh1,bh2,bh3, ad);
                LDSM4(bl0,bl1,bl2,bl3, ad + (AKL-AKH));
                uint32_t ba[2] = {bh0,bh1}, bb[2] = {bh2,bh3};
                uint32_t la[2] = {bl0,bl1}, lb[2] = {bl2,bl3};
                MMA_BF16(s_[2*jp],   qfh[k], ba);
                MMA_BF16(s_[2*jp],   qfl[k], ba);
                MMA_BF16(s_[2*jp],   qfh[k], la);
                MMA_BF16(s_[2*jp+1], qfh[k], bb);
                MMA_BF16(s_[2*jp+1], qfl[k], bb);
                MMA_BF16(s_[2*jp+1], qfh[k], lb);
            }
        }

        // ---- mask + online softmax ----
        float mx0 = -1e30f, mx1 = -1e30f;
        #pragma unroll
        for (int jf = 0; jf < 8; jf++) {
            #pragma unroll
            for (int cc = 0; cc < 2; cc++) {
                int g = ks + jf*8 + cb2 + cc;
                if (!(g <= t0 && g >= t0 - WINSZ)) s_[jf][cc]   = -1e30f;
                if (!(g <= t1 && g >= t1 - WINSZ)) s_[jf][2+cc] = -1e30f;
            }
            mx0 = fmaxf(mx0, fmaxf(s_[jf][0], s_[jf][1]));
            mx1 = fmaxf(mx1, fmaxf(s_[jf][2], s_[jf][3]));
        }
        mx0 = fmaxf(mx0, __shfl_xor_sync(0xffffffffu, mx0, 1));
        mx0 = fmaxf(mx0, __shfl_xor_sync(0xffffffffu, mx0, 2));
        mx1 = fmaxf(mx1, __shfl_xor_sync(0xffffffffu, mx1, 1));
        mx1 = fmaxf(mx1, __shfl_xor_sync(0xffffffffu, mx1, 2));
        float m0n = fmaxf(m0, mx0), m1n = fmaxf(m1, mx1);
        float c0 = exp2f((m0 - m0n)*LOG2E), c1 = exp2f((m1 - m1n)*LOG2E);

        float rs0 = 0.f, rs1 = 0.f;
        uint32_t pfh[4][4], pfl[4][4];
        #pragma unroll
        for (int kf = 0; kf < 4; kf++) {
            #pragma unroll
            for (int jj = 0; jj < 2; jj++) {
                const int jf = 2*kf + jj;
                float p0 = (s_[jf][0] > -1e29f) ? exp2f((s_[jf][0] - m0n)*LOG2E) : 0.f;
                float p1 = (s_[jf][1] > -1e29f) ? exp2f((s_[jf][1] - m0n)*LOG2E) : 0.f;
                float p2 = (s_[jf][2] > -1e29f) ? exp2f((s_[jf][2] - m1n)*LOG2E) : 0.f;
                float p3 = (s_[jf][3] > -1e29f) ? exp2f((s_[jf][3] - m1n)*LOG2E) : 0.f;
                rs0 += p0 + p1;
                rs1 += p2 + p3;
                __nv_bfloat16 h0,lo0,h1,lo1,h2,lo2,h3,lo3;
                split_bf16(p0,h0,lo0); split_bf16(p1,h1,lo1);
                split_bf16(p2,h2,lo2); split_bf16(p3,h3,lo3);
                __nv_bfloat162 hA(h0,h1), hB(h2,h3), lA(lo0,lo1), lB(lo2,lo3);
                pfh[kf][0 + 2*jj] = *(uint32_t*)&hA;   // rows r0: regs 0 (cols 0-7) / 2 (cols 8-15)
                pfh[kf][1 + 2*jj] = *(uint32_t*)&hB;   // rows r1
                pfl[kf][0 + 2*jj] = *(uint32_t*)&lA;
                pfl[kf][1 + 2*jj] = *(uint32_t*)&lB;
            }
        }
        rs0 += __shfl_xor_sync(0xffffffffu, rs0, 1);
        rs0 += __shfl_xor_sync(0xffffffffu, rs0, 2);
        rs1 += __shfl_xor_sync(0xffffffffu, rs1, 1);
        rs1 += __shfl_xor_sync(0xffffffffu, rs1, 2);
        l0 = l0*c0 + rs0;
        l1 = l1*c1 + rs1;
        m0 = m0n; m1 = m1n;
        #pragma unroll
        for (int j = 0; j < 16; j++) {
            o_[j][0] *= c0; o_[j][1] *= c0;
            o_[j][2] *= c1; o_[j][3] *= c1;
        }

        // ---- O += P V (bf16x3) ----
        #pragma unroll
        for (int jp = 0; jp < 8; jp++) {
            #pragma unroll
            for (int kf = 0; kf < 4; kf++) {
                uint32_t ad = kb_ + AVH + (uint32_t)((browB + jp*16)*72 + bcolB + kf*16)*2u;
                uint32_t vh0,vh1,vh2,vh3, vl0,vl1,vl2,vl3;
                LDSM4(vh0,vh1,vh2,vh3, ad);
                LDSM4(vl0,vl1,vl2,vl3, ad + (AVL-AVH));
                uint32_t va[2] = {vh0,vh1}, vb[2] = {vh2,vh3};
                uint32_t wa[2] = {vl0,vl1}, wb[2] = {vl2,vl3};
                MMA_BF16(o_[2*jp],   pfh[kf], va);
                MMA_BF16(o_[2*jp],   pfl[kf], va);
                MMA_BF16(o_[2*jp],   pfh[kf], wa);
                MMA_BF16(o_[2*jp+1], pfh[kf], vb);
                MMA_BF16(o_[2*jp+1], pfl[kf], vb);
                MMA_BF16(o_[2*jp+1], pfh[kf], wb);
            }
        }
        __syncthreads();
    }
    #undef LOAD_KV

    // ---- epilogue: normalize, split, store ----
    const float inv0 = 1.0f / l0;
    const float inv1 = 1.0f / l1;
    const size_t ob0 = ((size_t)(b*Tdim) + t0) * (QH*HD) + h*HD;
    const size_t ob1 = ((size_t)(b*Tdim) + t1) * (QH*HD) + h*HD;
    #pragma unroll
    for (int jn = 0; jn < 16; jn++) {
        int d = jn*8 + cb2;
        float y0 = o_[jn][0]*inv0, y1 = o_[jn][1]*inv0;
        float y2 = o_[jn][2]*inv1, y3 = o_[jn][3]*inv1;
        __nv_bfloat16 h0,lo0,h1,lo1,h2,lo2,h3,lo3;
        split_bf16(y0,h0,lo0); split_bf16(y1,h1,lo1);
        split_bf16(y2,h2,lo2); split_bf16(y3,h3,lo3);
        *(__nv_bfloat162*)(ohi + ob0 + d) = __nv_bfloat162(h0,h1);
        *(__nv_bfloat162*)(olo + ob0 + d) = __nv_bfloat162(lo0,lo1);
        *(__nv_bfloat162*)(ohi + ob1 + d) = __nv_bfloat162(h2,h3);
        *(__nv_bfloat162*)(olo + ob1 + d) = __nv_bfloat162(lo2,lo3);
    }
}

// ---------------------------------------------------------------------------
// launch
// ---------------------------------------------------------------------------
static void bgemm(const __nv_bfloat16* Ahi, const __nv_bfloat16* Alo,
                  const __nv_bfloat16* Whi, const __nv_bfloat16* Wlo,
                  const float* bias, const float* res, float* C, int N, int K) {
    dim3 grid(N / CTN, MROWS / CTM);
    if (bias) {
        bgemm_kernel<true,false><<<grid, 256, GEMM_SMEM_BYTES>>>(Ahi, Alo, Whi, Wlo, bias, res, C, N, K);
    } else if (res) {
        bgemm_kernel<false,true><<<grid, 256, GEMM_SMEM_BYTES>>>(Ahi, Alo, Whi, Wlo, bias, res, C, N, K);
    } else {
        bgemm_kernel<false,false><<<grid, 256, GEMM_SMEM_BYTES>>>(Ahi, Alo, Whi, Wlo, bias, res, C, N, K);
    }
}

extern "C" void kernel_launch(void* const* d_in, const int* in_sizes, int n_in,
                              void* d_out, int out_size) {
    const float* x         = (const float*)d_in[0];
    const float* gn_hawk   = (const float*)d_in[1];
    const float* gn_hgmlp  = (const float*)d_in[2];
    const float* gn_smqa   = (const float*)d_in[3];
    const float* gn_sgmlp  = (const float*)d_in[4];
    const float* hawk_Win  = (const float*)d_in[5];
    const float* hawk_cw   = (const float*)d_in[6];
    const float* hawk_cb   = (const float*)d_in[7];
    const float* hawk_Wg   = (const float*)d_in[8];
    const float* hawk_bg   = (const float*)d_in[9];
    const float* hawk_fb   = (const float*)d_in[10];
    const float* hawk_Wout = (const float*)d_in[11];
    const float* g1_Wgrow  = (const float*)d_in[12];
    const float* g1_Wshr   = (const float*)d_in[13];
    const float* g2_Wgrow  = (const float*)d_in[14];
    const float* g2_Wshr   = (const float*)d_in[15];
    const float* smqa_Wq   = (const float*)d_in[16];
    const float* smqa_Wkv  = (const float*)d_in[17];
    const float* smqa_Wout = (const float*)d_in[18];
    float* out = (float*)d_out;

    float *big, *mid, *small, *chA, *chS, *sIn;
    __nv_bfloat16 *Ahi, *Alo, *Whi, *Wlo;
    cudaGetSymbolAddress((void**)&big,   g_big);
    cudaGetSymbolAddress((void**)&mid,   g_mid);
    cudaGetSymbolAddress((void**)&small, g_small);
    cudaGetSymbolAddress((void**)&Ahi,   g_Ahi);
    cudaGetSymbolAddress((void**)&Alo,   g_Alo);
    cudaGetSymbolAddress((void**)&Whi,   g_Whi);
    cudaGetSymbolAddress((void**)&Wlo,   g_Wlo);
    cudaGetSymbolAddress((void**)&chA,   g_chA);
    cudaGetSymbolAddress((void**)&chS,   g_chS);
    cudaGetSymbolAddress((void**)&sIn,   g_sIn);

    cudaFuncSetAttribute((const void*)attn_hmma_kernel,
                         cudaFuncAttributeMaxDynamicSharedMemorySize, (int)ATT_SMEM);
    cudaFuncSetAttribute((const void*)bgemm_kernel<true,false>,
                         cudaFuncAttributeMaxDynamicSharedMemorySize, GEMM_SMEM_BYTES);
    cudaFuncSetAttribute((const void*)bgemm_kernel<false,true>,
                         cudaFuncAttributeMaxDynamicSharedMemorySize, GEMM_SMEM_BYTES);
    cudaFuncSetAttribute((const void*)bgemm_kernel<false,false>,
                         cudaFuncAttributeMaxDynamicSharedMemorySize, GEMM_SMEM_BYTES);

    const int EW = 256;
    #define CONVW(W, n) convw_kernel<<<((n)/4 + EW - 1)/EW, EW>>>((W), Whi, Wlo, (n)/4)

    // ---------------- stage 1: hawk ----------------
    rmsnorm_bf16_kernel<<<MROWS, 256>>>(x, gn_hawk, Ahi, Alo);
    CONVW(hawk_Win, 2*HID*DIM);
    bgemm(Ahi, Alo, Whi, Wlo, nullptr, nullptr, big, 2*HID, DIM);           // gh
    conv_kernel<<<(MROWS*HID)/EW, EW>>>(big, hawk_cw, hawk_cb, small, Ahi, Alo);
    CONVW(hawk_Wg, 2*HID*HID);
    bgemm(Ahi, Alo, Whi, Wlo, hawk_bg, nullptr, mid, 2*HID, HID);           // gi
    gates_kernel<<<(MROWS*HID)/EW, EW>>>(mid, small, hawk_fb);
    scanA_kernel<<<(Bdim*NCH*HID + EW - 1)/EW, EW>>>(mid, chA, chS);
    scanB_kernel<<<(Bdim*HID + EW - 1)/EW, EW>>>(chA, chS, sIn);
    scanC_kernel<<<(Bdim*NCH*HID + EW - 1)/EW, EW>>>(mid, big, sIn, Ahi, Alo);
    CONVW(hawk_Wout, DIM*HID);
    bgemm(Ahi, Alo, Whi, Wlo, nullptr, x, out, DIM, HID);                   // out = x + hy@Wout^T

    // ---------------- stage 2: gated MLP 1 ----------------
    rmsnorm_bf16_kernel<<<MROWS, 256>>>(out, gn_hgmlp, Ahi, Alo);
    CONVW(g1_Wgrow, 2*GH*DIM);
    bgemm(Ahi, Alo, Whi, Wlo, nullptr, nullptr, big, 2*GH, DIM);
    gelugate_kernel<<<(MROWS*GH)/EW, EW>>>(big, Ahi, Alo);
    CONVW(g1_Wshr, DIM*GH);
    bgemm(Ahi, Alo, Whi, Wlo, nullptr, out, out, DIM, GH);

    // ---------------- stage 3: sliding-window MQA ----------------
    rmsnorm_bf16_kernel<<<MROWS, 256>>>(out, gn_smqa, Ahi, Alo);
    float* qb  = big;
    float* kvb = big + (size_t)MROWS * (QH*HD);
    CONVW(smqa_Wq, QH*HD*DIM);
    bgemm(Ahi, Alo, Whi, Wlo, nullptr, nullptr, qb, QH*HD, DIM);
    CONVW(smqa_Wkv, 2*HD*DIM);
    bgemm(Ahi, Alo, Whi, Wlo, nullptr, nullptr, kvb, 2*HD, DIM);

    __nv_bfloat16* qhi  = (__nv_bfloat16*)mid;
    __nv_bfloat16* qlo  = (__nv_bfloat16*)(mid + 4194304);
    __nv_bfloat16* khi  = (__nv_bfloat16*)(mid + 8388608);
    __nv_bfloat16* klo  = (__nv_bfloat16*)(mid + 8912896);
    __nv_bfloat16* vthi = (__nv_bfloat16*)(mid + 9437184);
    __nv_bfloat16* vtlo = (__nv_bfloat16*)(mid + 9961472);
    {
        int total = MROWS*QH*(HD/2) + MROWS*(HD/2) + MROWS*HD;
        rotsplit_kernel<<<(total + EW - 1)/EW, EW>>>(qb, kvb, qhi, qlo, khi, klo, vthi, vtlo);
    }
    attn_hmma_kernel<<<dim3(Tdim/AQ, QH, Bdim), 256, ATT_SMEM>>>(
        qhi, qlo, khi, klo, vthi, vtlo, Ahi, Alo);
    CONVW(smqa_Wout, DIM*DIM);
    bgemm(Ahi, Alo, Whi, Wlo, nullptr, out, out, DIM, DIM);

    // ---------------- stage 4: gated MLP 2 ----------------
    rmsnorm_bf16_kernel<<<MROWS, 256>>>(out, gn_sgmlp, Ahi, Alo);
    CONVW(g2_Wgrow, 2*GH*DIM);
    bgemm(Ahi, Alo, Whi, Wlo, nullptr, nullptr, big, 2*GH, DIM);
    gelugate_kernel<<<(MROWS*GH)/EW, EW>>>(big, Ahi, Alo);
    CONVW(g2_Wshr, DIM*GH);
    bgemm(Ahi, Alo, Whi, Wlo, nullptr, out, out, DIM, GH);
    #undef CONVW
}